// round 2
// baseline (speedup 1.0000x reference)
#include <cuda_runtime.h>
#include <math.h>

// Problem constants
#define BB 4
#define NN 1024
#define CC 512
#define HH 8
#define DD 64
#define MR 4096            // B*N
#define TT 11              // conv taps (self + 10 neighbors)
#define KDIM 5632          // TT * CC

// ---------------- device scratch (allocation-free per harness rules) ----------------
__device__ float g_q[MR * CC];
__device__ float g_k[MR * CC];
__device__ float g_v[MR * CC];
__device__ float g_WT[KDIM * CC];
__device__ float g_conv[MR * CC];
__device__ float g_xloc[MR * CC];
__device__ float g_x[MR * CC];
__device__ float g_xn[MR * CC];
__device__ float g_km[BB * CC];
__device__ float g_kv[BB * HH * DD * DD];
__device__ double g_loss[3];

// ---------------- generic SGEMM: C = A(MxK) @ B(KxN) + bias, all row-major ----------
// Tiles: 64x64 output, BK=16, 256 threads, 4x4 per thread. M%64==N%64==0, K%16==0.
__global__ __launch_bounds__(256) void sgemm_bias(
    const float* __restrict__ A, const float* __restrict__ Bm,
    const float* __restrict__ bias, float* __restrict__ C,
    int M, int N, int K)
{
    __shared__ float As[16][65];   // padded: transposed A tile
    __shared__ float Bs[16][64];
    int tid = threadIdx.x;
    int tx = tid & 15, ty = tid >> 4;
    int bm = blockIdx.y << 6, bn = blockIdx.x << 6;
    int ar = tid >> 2, ac = (tid & 3) << 2;   // A tile: 64 rows x 16 cols, float4 per thread
    int br = tid >> 4, bc = (tid & 15) << 2;  // B tile: 16 rows x 64 cols
    float acc[4][4] = {};
    for (int k0 = 0; k0 < K; k0 += 16) {
        float4 av = *(const float4*)&A[(bm + ar) * K + k0 + ac];
        float4 bv = *(const float4*)&Bm[(k0 + br) * N + bn + bc];
        As[ac + 0][ar] = av.x; As[ac + 1][ar] = av.y;
        As[ac + 2][ar] = av.z; As[ac + 3][ar] = av.w;
        *(float4*)&Bs[br][bc] = bv;
        __syncthreads();
#pragma unroll
        for (int kk = 0; kk < 16; kk++) {
            float a[4];
#pragma unroll
            for (int i = 0; i < 4; i++) a[i] = As[kk][ty * 4 + i];
            float4 b4 = *(const float4*)&Bs[kk][tx * 4];
            float bb4[4] = {b4.x, b4.y, b4.z, b4.w};
#pragma unroll
            for (int i = 0; i < 4; i++)
#pragma unroll
                for (int j = 0; j < 4; j++)
                    acc[i][j] += a[i] * bb4[j];
        }
        __syncthreads();
    }
#pragma unroll
    for (int i = 0; i < 4; i++) {
        int row = bm + ty * 4 + i;
#pragma unroll
        for (int j = 0; j < 4; j++) {
            int col = bn + tx * 4 + j;
            C[row * N + col] = acc[i][j] + bias[col];
        }
    }
}

// ---------------- Wconv transpose: WT[(t*512+c)*512 + o] = Wconv[o,c,t] ----------------
__global__ void transpose_wconv(const float* __restrict__ W, float* __restrict__ WT) {
    int idx = blockIdx.x * 256 + threadIdx.x;
    if (idx >= KDIM * CC) return;
    int kk = idx >> 9, o = idx & 511;
    int t = kk >> 9, c = kk & 511;
    WT[idx] = W[o * KDIM + c * TT + t];
}

// ---------------- conv GEMM with fused neighbor gather ----------------
// conv[m, o] = sum_{t,c} feats[m, t, c] * Wconv[o, c, t]
// A operand gathered from v rows via adj; each BK=16 tile lies in a single tap t.
__global__ __launch_bounds__(256) void conv_gemm(
    const float* __restrict__ v, const int* __restrict__ adj,
    const float* __restrict__ WT, const float* __restrict__ bias,
    float* __restrict__ C)
{
    __shared__ float As[16][65];
    __shared__ float Bs[16][64];
    int tid = threadIdx.x;
    int tx = tid & 15, ty = tid >> 4;
    int bm = blockIdx.y << 6, bn = blockIdx.x << 6;
    int ar = tid >> 2, ac = (tid & 3) << 2;
    int br = tid >> 4, bc = (tid & 15) << 2;
    int gm = bm + ar;
    int bat = gm >> 10;
    float acc[4][4] = {};
    for (int k0 = 0; k0 < KDIM; k0 += 16) {
        int t = k0 >> 9;
        int cc = (k0 & 511) + ac;
        int srow = (t == 0) ? gm : ((bat << 10) + adj[gm * 10 + (t - 1)]);
        float4 av = *(const float4*)&v[srow * CC + cc];
        float4 bv = *(const float4*)&WT[(k0 + br) * CC + bn + bc];
        As[ac + 0][ar] = av.x; As[ac + 1][ar] = av.y;
        As[ac + 2][ar] = av.z; As[ac + 3][ar] = av.w;
        *(float4*)&Bs[br][bc] = bv;
        __syncthreads();
#pragma unroll
        for (int kk = 0; kk < 16; kk++) {
            float a[4];
#pragma unroll
            for (int i = 0; i < 4; i++) a[i] = As[kk][ty * 4 + i];
            float4 b4 = *(const float4*)&Bs[kk][tx * 4];
            float bb4[4] = {b4.x, b4.y, b4.z, b4.w};
#pragma unroll
            for (int i = 0; i < 4; i++)
#pragma unroll
                for (int j = 0; j < 4; j++)
                    acc[i][j] += a[i] * bb4[j];
        }
        __syncthreads();
    }
#pragma unroll
    for (int i = 0; i < 4; i++) {
        int row = bm + ty * 4 + i;
#pragma unroll
        for (int j = 0; j < 4; j++) {
            int col = bn + tx * 4 + j;
            C[row * CC + col] = acc[i][j] + bias[col];
        }
    }
}

// ---------------- q/k transform: relu+eps, /softplus(scale), focus (cube) ----------------
__device__ __forceinline__ float softplusf(float x) {
    return (x > 20.f) ? x : log1pf(expf(x));
}
__global__ void qk_focus(float* __restrict__ x, const float* __restrict__ scale_p) {
    int row = blockIdx.x;
    int tid = threadIdx.x; // 256
    __shared__ float red[256];
    float* p = x + row * CC;
    int c0 = tid, c1 = tid + 256;
    float v0 = fmaxf(p[c0], 0.f) + 1e-6f;
    float v1 = fmaxf(p[c1], 0.f) + 1e-6f;
    v0 /= softplusf(scale_p[c0]);
    v1 /= softplusf(scale_p[c1]);
    red[tid] = v0 * v0 + v1 * v1;
    __syncthreads();
    for (int o = 128; o; o >>= 1) {
        if (tid < o) red[tid] += red[tid + o];
        __syncthreads();
    }
    float nrm = sqrtf(red[0]);
    float inv = 1.f / (nrm + 1e-6f);
    float u0 = v0 * inv, u1 = v1 * inv;
    p[c0] = u0 * u0 * u0 * nrm;
    p[c1] = u1 * u1 * u1 * nrm;
}

// ---------------- kmean[b,c] = mean_n k[b,n,c] ----------------
__global__ void kmean_kernel(const float* __restrict__ k, float* __restrict__ km) {
    int b = blockIdx.y;
    int c = blockIdx.x * 256 + threadIdx.x;
    const float* p = k + b * NN * CC + c;
    float s = 0.f;
    for (int n = 0; n < NN; n++) s += p[n * CC];
    km[b * CC + c] = s * (1.f / NN);
}

// ---------------- kv[b,h,d,e] = sum_n k[b,n,h*64+d] * v[b,n,h*64+e] / N ----------------
__global__ __launch_bounds__(256) void kv_kernel(
    const float* __restrict__ k, const float* __restrict__ v, float* __restrict__ kv)
{
    int bh = blockIdx.x, b = bh >> 3, h = bh & 7;
    __shared__ float sk[8][64], sv[8][64];
    int t = threadIdx.x;
    int dI = (t >> 4) << 2, eI = (t & 15) << 2;
    const float* kb = k + b * NN * CC + h * 64;
    const float* vb = v + b * NN * CC + h * 64;
    float acc[4][4] = {};
    for (int n0 = 0; n0 < NN; n0 += 8) {
#pragma unroll
        for (int j = 0; j < 2; j++) {
            int idx = t + j * 256;
            int rr = idx >> 6, cc = idx & 63;
            sk[rr][cc] = kb[(n0 + rr) * CC + cc];
            sv[rr][cc] = vb[(n0 + rr) * CC + cc];
        }
        __syncthreads();
#pragma unroll
        for (int r = 0; r < 8; r++) {
            float a[4], bv4[4];
#pragma unroll
            for (int i = 0; i < 4; i++) a[i] = sk[r][dI + i];
#pragma unroll
            for (int j = 0; j < 4; j++) bv4[j] = sv[r][eI + j];
#pragma unroll
            for (int i = 0; i < 4; i++)
#pragma unroll
                for (int j = 0; j < 4; j++)
                    acc[i][j] += a[i] * bv4[j];
        }
        __syncthreads();
    }
    float invN = 1.f / NN;
#pragma unroll
    for (int i = 0; i < 4; i++)
#pragma unroll
        for (int j = 0; j < 4; j++)
            kv[(bh * 64 + dI + i) * 64 + eI + j] = acc[i][j] * invN;
}

// ---------------- attention output + x_local add ----------------
// x[b,n,h*64+e] = z[b,h,n] * sum_d q[b,n,h*64+d]*kv[b,h,d,e] + xloc
__global__ __launch_bounds__(512) void attn_kernel(
    const float* __restrict__ q, const float* __restrict__ km,
    const float* __restrict__ kv, const float* __restrict__ xloc,
    float* __restrict__ x)
{
    int row = blockIdx.x;
    int b = row >> 10;
    int c = threadIdx.x; // 512
    __shared__ float qs[512];
    __shared__ float ps[512];
    __shared__ float zs[8];
    float qv = q[row * CC + c];
    qs[c] = qv;
    ps[c] = qv * km[b * CC + c];
    __syncthreads();
    if (c < 8) {
        float s = 0.f;
#pragma unroll
        for (int d = 0; d < 64; d++) s += ps[c * 64 + d];
        zs[c] = 1.f / (s + 1e-6f);
    }
    __syncthreads();
    int h = c >> 6, e = c & 63;
    const float* kvp = kv + ((b * 8 + h) * 64) * 64 + e;
    float acc = 0.f;
#pragma unroll 8
    for (int d = 0; d < 64; d++) acc += qs[h * 64 + d] * kvp[d * 64];
    x[row * CC + c] = acc * zs[h] + xloc[row * CC + c];
}

// ---------------- disagreement: one warp per (b,h) ----------------
// contributes ||sum_n hn||^2 - sum_n ||hn||^2 into *out (double atomic)
__global__ void disagree_kernel(const float* __restrict__ x, int nRows, int rowStride,
                                int strideB, int strideH, double* __restrict__ out)
{
    int bh = blockIdx.x, b = bh >> 3, h = bh & 7;
    const float* p = x + b * strideB + h * strideH;
    int l = threadIdx.x; // 32
    double s0 = 0.0, s1 = 0.0, diag = 0.0;
    for (int n = 0; n < nRows; n++) {
        const float* r = p + n * rowStride;
        float v0 = r[l], v1 = r[l + 32];
        float sq = v0 * v0 + v1 * v1;
#pragma unroll
        for (int o = 16; o; o >>= 1) sq += __shfl_xor_sync(0xffffffffu, sq, o);
        float inv = 1.f / fmaxf(sqrtf(sq), 1e-12f);
        float h0 = v0 * inv, h1 = v1 * inv;
        s0 += (double)h0; s1 += (double)h1;
        diag += (double)(h0 * h0 + h1 * h1);
    }
    double val = s0 * s0 + s1 * s1;
#pragma unroll
    for (int o = 16; o; o >>= 1) {
        val += __shfl_xor_sync(0xffffffffu, val, o);
        diag += __shfl_xor_sync(0xffffffffu, diag, o);
    }
    if (l == 0) atomicAdd(out, val - diag);
}

// ---------------- LayerNorm over C ----------------
__global__ void ln_kernel(const float* __restrict__ x, const float* __restrict__ g,
                          const float* __restrict__ bta, float* __restrict__ xn)
{
    int row = blockIdx.x;
    int tid = threadIdx.x; // 256
    __shared__ float rs[256], rq[256];
    const float* p = x + row * CC;
    float v0 = p[tid], v1 = p[tid + 256];
    rs[tid] = v0 + v1;
    rq[tid] = v0 * v0 + v1 * v1;
    __syncthreads();
    for (int o = 128; o; o >>= 1) {
        if (tid < o) { rs[tid] += rs[tid + o]; rq[tid] += rq[tid + o]; }
        __syncthreads();
    }
    float mu = rs[0] * (1.f / CC);
    float var = rq[0] * (1.f / CC) - mu * mu;
    float inv = rsqrtf(var + 1e-5f);
    xn[row * CC + tid] = (v0 - mu) * inv * g[tid] + bta[tid];
    xn[row * CC + tid + 256] = (v1 - mu) * inv * g[tid + 256] + bta[tid + 256];
}

// ---------------- loss bookkeeping ----------------
__global__ void zero_loss(double* L) { if (threadIdx.x < 3) L[threadIdx.x] = 0.0; }

__global__ void finish_loss(const double* __restrict__ L, float* dst, int doWrite) {
    if (doWrite && threadIdx.x == 0) {
        double dbig = 32.0 * 1024.0 * 1024.0;   // B*H*N^2, N=1024
        double dsml = 32.0 * 64.0 * 64.0;       // B*H*N^2, N=64 (kv)
        dst[0] = (float)((L[0] / dbig + L[1] / dsml + L[2] / dbig) / 3.0);
    }
}

// ---------------- launch ----------------
extern "C" void kernel_launch(void* const* d_in, const int* in_sizes, int n_in,
                              void* d_out, int out_size)
{
    const float* Q      = (const float*)d_in[0];
    const int*   adj    = (const int*)  d_in[1];
    const float* Wq     = (const float*)d_in[2];
    const float* bq     = (const float*)d_in[3];
    const float* Wk     = (const float*)d_in[4];
    const float* bk     = (const float*)d_in[5];
    const float* Wv     = (const float*)d_in[6];
    const float* bv     = (const float*)d_in[7];
    const float* scp    = (const float*)d_in[8];
    const float* Wconv  = (const float*)d_in[9];
    const float* bconv  = (const float*)d_in[10];
    const float* W2     = (const float*)d_in[11];
    const float* b2     = (const float*)d_in[12];
    const float* ln_g   = (const float*)d_in[13];
    const float* ln_b   = (const float*)d_in[14];
    const float* Wo     = (const float*)d_in[15];
    const float* bo     = (const float*)d_in[16];
    float* out = (float*)d_out;

    float *q, *k, *v, *WT, *conv, *xloc, *x, *xn, *km, *kv;
    double* loss;
    cudaGetSymbolAddress((void**)&q,    g_q);
    cudaGetSymbolAddress((void**)&k,    g_k);
    cudaGetSymbolAddress((void**)&v,    g_v);
    cudaGetSymbolAddress((void**)&WT,   g_WT);
    cudaGetSymbolAddress((void**)&conv, g_conv);
    cudaGetSymbolAddress((void**)&xloc, g_xloc);
    cudaGetSymbolAddress((void**)&x,    g_x);
    cudaGetSymbolAddress((void**)&xn,   g_xn);
    cudaGetSymbolAddress((void**)&km,   g_km);
    cudaGetSymbolAddress((void**)&kv,   g_kv);
    cudaGetSymbolAddress((void**)&loss, g_loss);

    dim3 g512(CC / 64, MR / 64);   // (8, 64)

    zero_loss<<<1, 32>>>(loss);

    // projections
    sgemm_bias<<<g512, 256>>>(Q, Wq, bq, q, MR, CC, CC);
    sgemm_bias<<<g512, 256>>>(Q, Wk, bk, k, MR, CC, CC);
    sgemm_bias<<<g512, 256>>>(Q, Wv, bv, v, MR, CC, CC);

    // loss_local on head-view of raw v: base b*N*C + h*64, row stride C
    disagree_kernel<<<32, 32>>>(v, NN, CC, NN * CC, DD, loss + 0);

    // local branch: gather-fused conv GEMM then W2
    transpose_wconv<<<(KDIM * CC + 255) / 256, 256>>>(Wconv, WT);
    conv_gemm<<<g512, 256>>>(v, adj, WT, bconv, conv);
    sgemm_bias<<<g512, 256>>>(conv, W2, b2, xloc, MR, CC, CC);

    // q/k elementwise transform
    qk_focus<<<MR, 256>>>(q, scp);
    qk_focus<<<MR, 256>>>(k, scp);

    // kmean, kv
    kmean_kernel<<<dim3(2, BB), 256>>>(k, km);
    kv_kernel<<<32, 256>>>(k, v, kv);

    // loss_kv: kv rows contiguous, stride 64; base (b*8+h)*4096
    disagree_kernel<<<32, 32>>>(kv, DD, DD, HH * DD * DD, DD * DD, loss + 1);

    // attention out + local add
    attn_kernel<<<MR, 512>>>(q, km, kv, xloc, x);

    // loss_out on flat reshape view: base b*524288 + h*65536, contiguous rows of 64
    disagree_kernel<<<32, 32>>>(x, NN, DD, NN * CC, NN * CC / HH, loss + 2);

    // layernorm + output projection
    ln_kernel<<<MR, 256>>>(x, ln_g, ln_b, xn);
    sgemm_bias<<<g512, 256>>>(xn, Wo, bo, out, MR, CC, CC);

    // loss scalar appended after the (B,N,C) output, if the buffer has room
    finish_loss<<<1, 32>>>(loss, out + MR * CC, (out_size > MR * CC) ? 1 : 0);
}

// round 3
// speedup vs baseline: 1.1567x; 1.1567x over previous
#include <cuda_runtime.h>
#include <math.h>

// Problem constants
#define BB 4
#define NN 1024
#define CC 512
#define HH 8
#define DD 64
#define MR 4096            // B*N
#define TT 11              // conv taps (self + 10 neighbors)
#define KDIM 5632          // TT * CC

typedef unsigned long long ull;

// ---------------- device scratch ----------------
__device__ float g_q[MR * CC];
__device__ float g_k[MR * CC];
__device__ float g_v[MR * CC];
__device__ float g_WT[KDIM * CC];
__device__ float g_conv[MR * CC];
__device__ float g_xloc[MR * CC];
__device__ float g_x[MR * CC];
__device__ float g_xn[MR * CC];
__device__ float g_km[BB * CC];
__device__ float g_kv[BB * HH * DD * DD];
__device__ float g_kvp[8 * BB * HH * DD * DD];
__device__ float g_pvec[32 * 32 * 64];
__device__ float g_pdiag[32 * 32];
__device__ float g_invs[CC];
__device__ double g_lossbh[96];

// ---------------- packed f32x2 helpers ----------------
__device__ __forceinline__ ull pk2(float lo, float hi) {
    ull r; asm("mov.b64 %0, {%1,%2};" : "=l"(r) : "f"(lo), "f"(hi)); return r;
}
__device__ __forceinline__ void fma2(ull& acc, ull a, ull b) {
    asm("fma.rn.f32x2 %0, %1, %2, %0;" : "+l"(acc) : "l"(a), "l"(b));
}
__device__ __forceinline__ float2 up2(ull v) {
    float2 f; asm("mov.b64 {%0,%1}, %2;" : "=f"(f.x), "=f"(f.y) : "l"(v)); return f;
}

// ---------------- inner product macro over the 8x8 thread tile ----------------
#define TILE_COMPUTE(AS, BS)                                              \
    _Pragma("unroll")                                                     \
    for (int kk = 0; kk < 8; kk++) {                                      \
        float4 a0 = *(const float4*)&AS[kk][ty8];                         \
        float4 a1 = *(const float4*)&AS[kk][ty8 + 4];                     \
        float4 b0 = *(const float4*)&BS[kk][tx8];                         \
        float4 b1 = *(const float4*)&BS[kk][tx8 + 4];                     \
        ull bp[4];                                                        \
        bp[0] = pk2(b0.x, b0.y); bp[1] = pk2(b0.z, b0.w);                 \
        bp[2] = pk2(b1.x, b1.y); bp[3] = pk2(b1.z, b1.w);                 \
        float av[8] = {a0.x, a0.y, a0.z, a0.w, a1.x, a1.y, a1.z, a1.w};   \
        _Pragma("unroll")                                                 \
        for (int i = 0; i < 8; i++) {                                     \
            ull ap = pk2(av[i], av[i]);                                   \
            fma2(acc[i][0], ap, bp[0]); fma2(acc[i][1], ap, bp[1]);       \
            fma2(acc[i][2], ap, bp[2]); fma2(acc[i][3], ap, bp[3]);       \
        }                                                                 \
    }

// ---------------- SGEMM: C = A(MxK) @ B(KxN) + bias. 128x128 tile, BK=8 ----------------
__global__ __launch_bounds__(256) void sgemm_bias(
    const float* __restrict__ A, const float* __restrict__ Bm,
    const float* __restrict__ bias, float* __restrict__ C,
    int M, int N, int K)
{
    __shared__ float As[2][8][128];
    __shared__ float Bs[2][8][128];
    const int tid = threadIdx.x;
    const int tx8 = (tid & 15) * 8;
    const int ty8 = (tid >> 4) * 8;
    const int bm = blockIdx.y * 128, bn = blockIdx.x * 128;
    const int arow = tid >> 1, acol = (tid & 1) * 4;
    const int brow = tid >> 5, bcol = (tid & 31) * 4;
    ull acc[8][4] = {};

    float4 ra = *(const float4*)&A[(bm + arow) * K + acol];
    float4 rb = *(const float4*)&Bm[brow * N + bn + bcol];
    As[0][acol + 0][arow] = ra.x; As[0][acol + 1][arow] = ra.y;
    As[0][acol + 2][arow] = ra.z; As[0][acol + 3][arow] = ra.w;
    *(float4*)&Bs[0][brow][bcol] = rb;
    __syncthreads();

    int nIter = K >> 3;
    for (int it = 0; it < nIter; ++it) {
        int cur = it & 1;
        bool more = (it + 1 < nIter);
        if (more) {
            int k0 = (it + 1) << 3;
            ra = *(const float4*)&A[(bm + arow) * K + k0 + acol];
            rb = *(const float4*)&Bm[(k0 + brow) * N + bn + bcol];
        }
        TILE_COMPUTE(As[cur], Bs[cur]);
        if (more) {
            int nxt = cur ^ 1;
            As[nxt][acol + 0][arow] = ra.x; As[nxt][acol + 1][arow] = ra.y;
            As[nxt][acol + 2][arow] = ra.z; As[nxt][acol + 3][arow] = ra.w;
            *(float4*)&Bs[nxt][brow][bcol] = rb;
        }
        __syncthreads();
    }
#pragma unroll
    for (int i = 0; i < 8; i++) {
        int row = bm + ty8 + i;
#pragma unroll
        for (int j = 0; j < 4; j++) {
            float2 f = up2(acc[i][j]);
            int col = bn + tx8 + j * 2;
            C[row * N + col]     = f.x + bias[col];
            C[row * N + col + 1] = f.y + bias[col + 1];
        }
    }
}

// ---------------- conv GEMM with fused neighbor gather (K=5632, N=512) ----------------
__global__ __launch_bounds__(256) void conv_gemm(
    const float* __restrict__ v, const int* __restrict__ adj,
    const float* __restrict__ WT, const float* __restrict__ bias,
    float* __restrict__ C)
{
    __shared__ float As[2][8][128];
    __shared__ float Bs[2][8][128];
    const int tid = threadIdx.x;
    const int tx8 = (tid & 15) * 8;
    const int ty8 = (tid >> 4) * 8;
    const int bm = blockIdx.y * 128, bn = blockIdx.x * 128;
    const int arow = tid >> 1, acol = (tid & 1) * 4;
    const int brow = tid >> 5, bcol = (tid & 31) * 4;
    const int gm = bm + arow;
    const int bat = gm >> 10;
    ull acc[8][4] = {};

    // tile 0: tap 0 (self)
    float4 ra = *(const float4*)&v[gm * CC + acol];
    float4 rb = *(const float4*)&WT[brow * CC + bn + bcol];
    As[0][acol + 0][arow] = ra.x; As[0][acol + 1][arow] = ra.y;
    As[0][acol + 2][arow] = ra.z; As[0][acol + 3][arow] = ra.w;
    *(float4*)&Bs[0][brow][bcol] = rb;
    __syncthreads();

    const int nIter = KDIM >> 3;   // 704
    for (int it = 0; it < nIter; ++it) {
        int cur = it & 1;
        bool more = (it + 1 < nIter);
        if (more) {
            int k0 = (it + 1) << 3;
            int tap = k0 >> 9;
            int cc = (k0 & 511) + acol;
            int srow = (tap == 0) ? gm : ((bat << 10) + adj[gm * 10 + tap - 1]);
            ra = *(const float4*)&v[srow * CC + cc];
            rb = *(const float4*)&WT[(k0 + brow) * CC + bn + bcol];
        }
        TILE_COMPUTE(As[cur], Bs[cur]);
        if (more) {
            int nxt = cur ^ 1;
            As[nxt][acol + 0][arow] = ra.x; As[nxt][acol + 1][arow] = ra.y;
            As[nxt][acol + 2][arow] = ra.z; As[nxt][acol + 3][arow] = ra.w;
            *(float4*)&Bs[nxt][brow][bcol] = rb;
        }
        __syncthreads();
    }
#pragma unroll
    for (int i = 0; i < 8; i++) {
        int row = bm + ty8 + i;
#pragma unroll
        for (int j = 0; j < 4; j++) {
            float2 f = up2(acc[i][j]);
            int col = bn + tx8 + j * 2;
            C[row * CC + col]     = f.x + bias[col];
            C[row * CC + col + 1] = f.y + bias[col + 1];
        }
    }
}

// ---------------- Wconv transpose: WT[(t*512+c)*512 + o] = Wconv[o,c,t] ----------------
__global__ void transpose_wconv(const float* __restrict__ W, float* __restrict__ WT) {
    int idx = blockIdx.x * 256 + threadIdx.x;
    if (idx >= KDIM * CC) return;
    int kk = idx >> 9, o = idx & 511;
    int t = kk >> 9, c = kk & 511;
    WT[idx] = W[o * KDIM + c * TT + t];
}

// ---------------- 1/softplus(scale) precompute ----------------
__device__ __forceinline__ float softplusf(float x) {
    return (x > 20.f) ? x : log1pf(expf(x));
}
__global__ void invs_kernel(const float* __restrict__ scp, float* __restrict__ invs) {
    int c = blockIdx.x * 256 + threadIdx.x;
    if (c < CC) invs[c] = 1.f / softplusf(scp[c]);
}

// ---------------- q/k transform: relu+eps, *invscale, focus (cube) ----------------
__global__ void qk_focus(float* __restrict__ x, const float* __restrict__ invs) {
    int row = blockIdx.x;
    int tid = threadIdx.x; // 256
    __shared__ float red[256];
    float* p = x + row * CC;
    int c0 = tid, c1 = tid + 256;
    float v0 = (fmaxf(p[c0], 0.f) + 1e-6f) * invs[c0];
    float v1 = (fmaxf(p[c1], 0.f) + 1e-6f) * invs[c1];
    red[tid] = v0 * v0 + v1 * v1;
    __syncthreads();
    for (int o = 128; o; o >>= 1) {
        if (tid < o) red[tid] += red[tid + o];
        __syncthreads();
    }
    float nrm = sqrtf(red[0]);
    float inv = 1.f / (nrm + 1e-6f);
    float u0 = v0 * inv, u1 = v1 * inv;
    p[c0] = u0 * u0 * u0 * nrm;
    p[c1] = u1 * u1 * u1 * nrm;
}

// ---------------- kmean[b,c] = mean_n k[b,n,c] ----------------
__global__ void kmean_kernel(const float* __restrict__ k, float* __restrict__ km) {
    int b = blockIdx.y;
    int c = blockIdx.x * 256 + threadIdx.x;
    const float* p = k + b * NN * CC + c;
    float s = 0.f;
    for (int n = 0; n < NN; n++) s += p[n * CC];
    km[b * CC + c] = s * (1.f / NN);
}

// ---------------- kv partials: 8 N-splits of 128 rows each ----------------
__global__ __launch_bounds__(256) void kv_part(
    const float* __restrict__ k, const float* __restrict__ v, float* __restrict__ kvp)
{
    int bh = blockIdx.x, b = bh >> 3, h = bh & 7;
    int sp = blockIdx.y;
    __shared__ float sk[8][64], sv[8][64];
    int t = threadIdx.x;
    int dI = (t >> 4) << 2, eI = (t & 15) << 2;
    const float* kb = k + b * NN * CC + h * 64;
    const float* vb = v + b * NN * CC + h * 64;
    float acc[4][4] = {};
    int n0s = sp * 128, n0e = n0s + 128;
    for (int n0 = n0s; n0 < n0e; n0 += 8) {
#pragma unroll
        for (int j = 0; j < 2; j++) {
            int idx = t + j * 256;
            int rr = idx >> 6, cc = idx & 63;
            sk[rr][cc] = kb[(n0 + rr) * CC + cc];
            sv[rr][cc] = vb[(n0 + rr) * CC + cc];
        }
        __syncthreads();
#pragma unroll
        for (int r = 0; r < 8; r++) {
            float a[4], bv4[4];
#pragma unroll
            for (int i = 0; i < 4; i++) a[i] = sk[r][dI + i];
#pragma unroll
            for (int j = 0; j < 4; j++) bv4[j] = sv[r][eI + j];
#pragma unroll
            for (int i = 0; i < 4; i++)
#pragma unroll
                for (int j = 0; j < 4; j++)
                    acc[i][j] += a[i] * bv4[j];
        }
        __syncthreads();
    }
    float* dst = kvp + (sp * 32 + bh) * 4096;
#pragma unroll
    for (int i = 0; i < 4; i++)
#pragma unroll
        for (int j = 0; j < 4; j++)
            dst[(dI + i) * 64 + eI + j] = acc[i][j];
}

__global__ void kv_reduce(const float* __restrict__ kvp, float* __restrict__ kv) {
    int idx = blockIdx.x * 256 + threadIdx.x;   // 131072
    float s = 0.f;
#pragma unroll
    for (int sp = 0; sp < 8; sp++) s += kvp[sp * 131072 + idx];
    kv[idx] = s * (1.f / NN);
}

// ---------------- attention output + x_local add ----------------
__global__ __launch_bounds__(512) void attn_kernel(
    const float* __restrict__ q, const float* __restrict__ km,
    const float* __restrict__ kv, const float* __restrict__ xloc,
    float* __restrict__ x)
{
    int row = blockIdx.x;
    int b = row >> 10;
    int c = threadIdx.x; // 512
    __shared__ float qs[512];
    __shared__ float ps[512];
    __shared__ float zs[8];
    float qv = q[row * CC + c];
    qs[c] = qv;
    ps[c] = qv * km[b * CC + c];
    __syncthreads();
    if (c < 8) {
        float s = 0.f;
#pragma unroll
        for (int d = 0; d < 64; d++) s += ps[c * 64 + d];
        zs[c] = 1.f / (s + 1e-6f);
    }
    __syncthreads();
    int h = c >> 6, e = c & 63;
    const float* kvp = kv + ((b * 8 + h) * 64) * 64 + e;
    float acc = 0.f;
#pragma unroll 8
    for (int d = 0; d < 64; d++) acc += qs[h * 64 + d] * kvp[d * 64];
    x[row * CC + c] = acc * zs[h] + xloc[row * CC + c];
}

// ---------------- disagreement phase 1: per-(bh, split) partial vec + diag ----------------
// grid (32, 32), 32 threads; each block handles nRows/32 rows.
__global__ void disagree_part(const float* __restrict__ x, int rowsPerBlk, int rowStride,
                              int strideB, int strideH,
                              float* __restrict__ pvec, float* __restrict__ pdiag)
{
    int bh = blockIdx.x, b = bh >> 3, h = bh & 7;
    int s = blockIdx.y, S = gridDim.y;
    const float* p = x + b * strideB + h * strideH + s * rowsPerBlk * rowStride;
    int l = threadIdx.x; // 32
    float s0 = 0.f, s1 = 0.f, diag = 0.f;
    for (int n = 0; n < rowsPerBlk; n++) {
        const float* r = p + n * rowStride;
        float v0 = r[l], v1 = r[l + 32];
        float sq = v0 * v0 + v1 * v1;
#pragma unroll
        for (int o = 16; o; o >>= 1) sq += __shfl_xor_sync(0xffffffffu, sq, o);
        float inv = 1.f / fmaxf(sqrtf(sq), 1e-12f);
        float h0 = v0 * inv, h1 = v1 * inv;
        s0 += h0; s1 += h1;
        diag += h0 * h0 + h1 * h1;
    }
    float* pv = pvec + (bh * S + s) * 64;
    pv[l] = s0; pv[l + 32] = s1;
#pragma unroll
    for (int o = 16; o; o >>= 1) diag += __shfl_xor_sync(0xffffffffu, diag, o);
    if (l == 0) pdiag[bh * S + s] = diag;
}

// phase 2: one block per bh, 64 threads; writes Lb[bh] = ||sum||^2 - diag
__global__ void disagree_reduce(const float* __restrict__ pvec, const float* __restrict__ pdiag,
                                int S, double* __restrict__ Lb)
{
    int bh = blockIdx.x;
    int l = threadIdx.x; // 64
    double v = 0.0;
    for (int s = 0; s < S; s++) v += (double)pvec[(bh * S + s) * 64 + l];
    __shared__ double sh[64];
    sh[l] = v * v;
    __syncthreads();
    for (int o = 32; o; o >>= 1) {
        if (l < o) sh[l] += sh[l + o];
        __syncthreads();
    }
    if (l == 0) {
        double d = 0.0;
        for (int s = 0; s < S; s++) d += (double)pdiag[bh * S + s];
        Lb[bh] = sh[0] - d;
    }
}

// ---------------- small disagreement (kv, 64 rows): one warp per bh ----------------
__global__ void disagree_small(const float* __restrict__ x, int nRows, int rowStride,
                               int strideB, int strideH, double* __restrict__ Lb)
{
    int bh = blockIdx.x, b = bh >> 3, h = bh & 7;
    const float* p = x + b * strideB + h * strideH;
    int l = threadIdx.x; // 32
    double s0 = 0.0, s1 = 0.0, diag = 0.0;
    for (int n = 0; n < nRows; n++) {
        const float* r = p + n * rowStride;
        float v0 = r[l], v1 = r[l + 32];
        float sq = v0 * v0 + v1 * v1;
#pragma unroll
        for (int o = 16; o; o >>= 1) sq += __shfl_xor_sync(0xffffffffu, sq, o);
        float inv = 1.f / fmaxf(sqrtf(sq), 1e-12f);
        float h0 = v0 * inv, h1 = v1 * inv;
        s0 += (double)h0; s1 += (double)h1;
        diag += (double)(h0 * h0 + h1 * h1);
    }
    double val = s0 * s0 + s1 * s1;
#pragma unroll
    for (int o = 16; o; o >>= 1) {
        val += __shfl_xor_sync(0xffffffffu, val, o);
        diag += __shfl_xor_sync(0xffffffffu, diag, o);
    }
    if (l == 0) Lb[bh] = val - diag;
}

// ---------------- LayerNorm over C ----------------
__global__ void ln_kernel(const float* __restrict__ x, const float* __restrict__ g,
                          const float* __restrict__ bta, float* __restrict__ xn)
{
    int row = blockIdx.x;
    int tid = threadIdx.x; // 256
    __shared__ float rs[256], rq[256];
    const float* p = x + row * CC;
    float v0 = p[tid], v1 = p[tid + 256];
    rs[tid] = v0 + v1;
    rq[tid] = v0 * v0 + v1 * v1;
    __syncthreads();
    for (int o = 128; o; o >>= 1) {
        if (tid < o) { rs[tid] += rs[tid + o]; rq[tid] += rq[tid + o]; }
        __syncthreads();
    }
    float mu = rs[0] * (1.f / CC);
    float var = rq[0] * (1.f / CC) - mu * mu;
    float inv = rsqrtf(var + 1e-5f);
    xn[row * CC + tid] = (v0 - mu) * inv * g[tid] + bta[tid];
    xn[row * CC + tid + 256] = (v1 - mu) * inv * g[tid + 256] + bta[tid + 256];
}

// ---------------- final loss combine (deterministic serial sum) ----------------
__global__ void finish_loss(const double* __restrict__ Lb, float* dst, int doWrite) {
    if (doWrite && threadIdx.x == 0 && blockIdx.x == 0) {
        double l0 = 0.0, l1 = 0.0, l2 = 0.0;
        for (int i = 0; i < 32; i++) { l0 += Lb[i]; l1 += Lb[32 + i]; l2 += Lb[64 + i]; }
        double dbig = 4.0 * 8.0 * 1024.0 * 1024.0;
        double dsml = 4.0 * 8.0 * 64.0 * 64.0;
        dst[0] = (float)((l0 / dbig + l1 / dsml + l2 / dbig) / 3.0);
    }
}

// ---------------- launch ----------------
extern "C" void kernel_launch(void* const* d_in, const int* in_sizes, int n_in,
                              void* d_out, int out_size)
{
    const float* Q      = (const float*)d_in[0];
    const int*   adj    = (const int*)  d_in[1];
    const float* Wq     = (const float*)d_in[2];
    const float* bq     = (const float*)d_in[3];
    const float* Wk     = (const float*)d_in[4];
    const float* bk     = (const float*)d_in[5];
    const float* Wv     = (const float*)d_in[6];
    const float* bv     = (const float*)d_in[7];
    const float* scp    = (const float*)d_in[8];
    const float* Wconv  = (const float*)d_in[9];
    const float* bconv  = (const float*)d_in[10];
    const float* b2     = (const float*)d_in[12];
    const float* W2     = (const float*)d_in[11];
    const float* ln_g   = (const float*)d_in[13];
    const float* ln_b   = (const float*)d_in[14];
    const float* Wo     = (const float*)d_in[15];
    const float* bo     = (const float*)d_in[16];
    float* out = (float*)d_out;

    float *q, *k, *v, *WT, *conv, *xloc, *x, *xn, *km, *kv, *kvp, *pvec, *pdiag, *invs;
    double* Lb;
    cudaGetSymbolAddress((void**)&q,     g_q);
    cudaGetSymbolAddress((void**)&k,     g_k);
    cudaGetSymbolAddress((void**)&v,     g_v);
    cudaGetSymbolAddress((void**)&WT,    g_WT);
    cudaGetSymbolAddress((void**)&conv,  g_conv);
    cudaGetSymbolAddress((void**)&xloc,  g_xloc);
    cudaGetSymbolAddress((void**)&x,     g_x);
    cudaGetSymbolAddress((void**)&xn,    g_xn);
    cudaGetSymbolAddress((void**)&km,    g_km);
    cudaGetSymbolAddress((void**)&kv,    g_kv);
    cudaGetSymbolAddress((void**)&kvp,   g_kvp);
    cudaGetSymbolAddress((void**)&pvec,  g_pvec);
    cudaGetSymbolAddress((void**)&pdiag, g_pdiag);
    cudaGetSymbolAddress((void**)&invs,  g_invs);
    cudaGetSymbolAddress((void**)&Lb,    g_lossbh);

    dim3 gGemm(CC / 128, MR / 128);   // (4, 32)

    invs_kernel<<<2, 256>>>(scp, invs);

    // projections
    sgemm_bias<<<gGemm, 256>>>(Q, Wq, bq, q, MR, CC, CC);
    sgemm_bias<<<gGemm, 256>>>(Q, Wk, bk, k, MR, CC, CC);
    sgemm_bias<<<gGemm, 256>>>(Q, Wv, bv, v, MR, CC, CC);

    // loss_local on head-view of v: base b*N*C + h*64, row stride C
    disagree_part<<<dim3(32, 32), 32>>>(v, NN / 32, CC, NN * CC, DD, pvec, pdiag);
    disagree_reduce<<<32, 64>>>(pvec, pdiag, 32, Lb + 0);

    // local branch: gather-fused conv GEMM then W2
    transpose_wconv<<<(KDIM * CC + 255) / 256, 256>>>(Wconv, WT);
    conv_gemm<<<gGemm, 256>>>(v, adj, WT, bconv, conv);
    sgemm_bias<<<gGemm, 256>>>(conv, W2, b2, xloc, MR, CC, CC);

    // q/k elementwise transform
    qk_focus<<<MR, 256>>>(q, invs);
    qk_focus<<<MR, 256>>>(k, invs);

    // kmean, kv
    kmean_kernel<<<dim3(2, BB), 256>>>(k, km);
    kv_part<<<dim3(32, 8), 256>>>(k, v, kvp);
    kv_reduce<<<512, 256>>>(kvp, kv);

    // loss_kv
    disagree_small<<<32, 32>>>(kv, DD, DD, HH * DD * DD, DD * DD, Lb + 32);

    // attention out + local add
    attn_kernel<<<MR, 512>>>(q, km, kv, xloc, x);

    // loss_out on flat reshape view: base b*524288 + h*65536, contiguous rows of 64
    disagree_part<<<dim3(32, 32), 32>>>(x, NN / 32, DD, NN * CC, NN * CC / HH, pvec, pdiag);
    disagree_reduce<<<32, 64>>>(pvec, pdiag, 32, Lb + 64);

    // layernorm + output projection
    ln_kernel<<<MR, 256>>>(x, ln_g, ln_b, xn);
    sgemm_bias<<<gGemm, 256>>>(xn, Wo, bo, out, MR, CC, CC);

    // loss scalar appended after the (B,N,C) output, if the buffer has room
    finish_loss<<<1, 32>>>(Lb, out + MR * CC, (out_size > MR * CC) ? 1 : 0);
}

// round 5
// speedup vs baseline: 2.6048x; 2.2520x over previous
#include <cuda_runtime.h>
#include <math.h>
#include <stdint.h>
#include <mma.h>

using namespace nvcuda;

// Problem constants
#define BB 4
#define NN 1024
#define CC 512
#define HH 8
#define DD 64
#define MR 4096            // B*N
#define TT 11              // conv taps (self + 10 neighbors)
#define KDIM 5632          // TT * CC

typedef unsigned long long ull;

// ---------------- device scratch ----------------
__device__ float g_q[MR * CC];
__device__ float g_k[MR * CC];
__device__ float g_v[MR * CC];
__device__ float g_WT[KDIM * CC];        // conv weight, [o][t*512+c] tf32
__device__ float g_WqT[CC * CC];
__device__ float g_WkT[CC * CC];
__device__ float g_WvT[CC * CC];
__device__ float g_W2T[CC * CC];
__device__ float g_WoT[CC * CC];
__device__ float g_conv[MR * CC];
__device__ float g_xloc[MR * CC];
__device__ float g_x[MR * CC];
__device__ float g_xn[MR * CC];
__device__ float g_km[BB * CC];
__device__ float g_kmp[BB * 8 * CC];
__device__ float g_kv[BB * HH * DD * DD];
__device__ float g_kvp[8 * BB * HH * DD * DD];
__device__ float g_pvec[32 * 32 * 64];
__device__ float g_pdiag[32 * 32];
__device__ float g_invs[CC];
__device__ double g_lossbh[96];

// ---------------- tf32 round helper ----------------
__device__ __forceinline__ float to_tf32(float x) {
    unsigned u;
    asm("cvt.rna.tf32.f32 %0, %1;" : "=r"(u) : "f"(x));
    return __uint_as_float(u);
}

// ---------------- wmma tf32 GEMM core ----------------
// D[128x128] tile per CTA. 256 threads = 8 warps in 4(m) x 2(n); warp tile 32x64.
// A: fp32 MxK row-major, tf32-rounded on load. adj != null => conv gather path.
// BT: [n][k] tf32-prerounded. C row-major with N-stride 512. K % 16 == 0.
#define BKP 20        // padded k-stride in smem (floats); 80B rows, 16B-aligned

__device__ __forceinline__ void gemm_core(
    const float* __restrict__ A, const float* __restrict__ BT,
    const float* __restrict__ bias, float* __restrict__ C,
    int K, const int* __restrict__ adj)
{
    __shared__ float As[2][128 * BKP];
    __shared__ float Bs[2][128 * BKP];

    const int tid = threadIdx.x;          // 256
    const int wid = tid >> 5, lane = tid & 31;
    const int bm = blockIdx.y * 128, bn = blockIdx.x * 128;
    const int wm = (wid & 3) * 32;        // warp m-offset in tile
    const int wn = (wid >> 2) * 64;       // warp n-offset in tile
    const int bat = bm >> 10;             // batch id (1024 rows per batch)

    wmma::fragment<wmma::accumulator, 16, 16, 8, float> acc[2][4];
#pragma unroll
    for (int i = 0; i < 2; i++)
#pragma unroll
        for (int j = 0; j < 4; j++)
            wmma::fill_fragment(acc[i][j], 0.0f);

    const int T = K >> 4;                 // BK=16 stages

    // tile loader: 512 float4 (A) + 512 float4 (B), 2 per thread each
#define LOAD_TILES(IT, BUF)                                                   \
    {                                                                         \
        const int k0 = (IT) << 4;                                             \
        int tap = 0, kin = k0;                                                \
        if (adj) { tap = k0 >> 9; kin = k0 & 511; }                           \
        _Pragma("unroll")                                                     \
        for (int i = 0; i < 2; i++) {                                         \
            int f = tid + i * 256;                                            \
            int row = f >> 2, c4 = f & 3;                                     \
            const float* srcA;                                                \
            if (adj) {                                                        \
                int gm = bm + row;                                            \
                int srow = tap ? ((bat << 10) + adj[gm * 10 + tap - 1]) : gm; \
                srcA = A + (size_t)srow * 512 + kin + c4 * 4;                 \
            } else {                                                          \
                srcA = A + (size_t)(bm + row) * K + k0 + c4 * 4;              \
            }                                                                 \
            float4 av = *(const float4*)srcA;                                 \
            av.x = to_tf32(av.x); av.y = to_tf32(av.y);                       \
            av.z = to_tf32(av.z); av.w = to_tf32(av.w);                       \
            *(float4*)&As[BUF][row * BKP + c4 * 4] = av;                      \
            float4 bv = *(const float4*)(BT + (size_t)(bn + row) * K          \
                                            + k0 + c4 * 4);                  \
            *(float4*)&Bs[BUF][row * BKP + c4 * 4] = bv;                      \
        }                                                                     \
    }

    LOAD_TILES(0, 0);
    __syncthreads();

    for (int it = 0; it < T; ++it) {
        int buf = it & 1;
        if (it + 1 < T) LOAD_TILES(it + 1, buf ^ 1);
#pragma unroll
        for (int kk = 0; kk < 2; kk++) {
            wmma::fragment<wmma::matrix_a, 16, 16, 8, wmma::precision::tf32,
                           wmma::row_major> afr[2];
            wmma::fragment<wmma::matrix_b, 16, 16, 8, wmma::precision::tf32,
                           wmma::col_major> bfr[4];
#pragma unroll
            for (int i = 0; i < 2; i++)
                wmma::load_matrix_sync(afr[i], &As[buf][(wm + i * 16) * BKP + kk * 8], BKP);
#pragma unroll
            for (int j = 0; j < 4; j++)
                wmma::load_matrix_sync(bfr[j], &Bs[buf][(wn + j * 16) * BKP + kk * 8], BKP);
#pragma unroll
            for (int i = 0; i < 2; i++)
#pragma unroll
                for (int j = 0; j < 4; j++)
                    wmma::mma_sync(acc[i][j], afr[i], bfr[j], acc[i][j]);
        }
        __syncthreads();
    }

    // epilogue: stage each 16x16 accum through per-warp smem, add bias, write fp32
    float* stage = &As[0][0] + wid * (16 * BKP);   // 8 warps * 320 floats = As[0]
#pragma unroll
    for (int i = 0; i < 2; i++) {
#pragma unroll
        for (int j = 0; j < 4; j++) {
            wmma::store_matrix_sync(stage, acc[i][j], BKP, wmma::mem_row_major);
            __syncwarp();
#pragma unroll
            for (int t = 0; t < 8; t++) {
                int idx = lane * 8 + t;
                int r = idx >> 4, col = idx & 15;
                int gr = bm + wm + i * 16 + r;
                int gc = bn + wn + j * 16 + col;
                C[(size_t)gr * 512 + gc] = stage[r * BKP + col] + bias[gc];
            }
            __syncwarp();
        }
    }
#undef LOAD_TILES
}

__global__ __launch_bounds__(256) void gemm_qkv(
    const float* __restrict__ Q,
    const float* __restrict__ WqT, const float* __restrict__ WkT, const float* __restrict__ WvT,
    const float* __restrict__ bq, const float* __restrict__ bk, const float* __restrict__ bv,
    float* __restrict__ q, float* __restrict__ k, float* __restrict__ v)
{
    int z = blockIdx.z;
    const float* W = (z == 0) ? WqT : ((z == 1) ? WkT : WvT);
    const float* b = (z == 0) ? bq : ((z == 1) ? bk : bv);
    float* o = (z == 0) ? q : ((z == 1) ? k : v);
    gemm_core(Q, W, b, o, 512, nullptr);
}

__global__ __launch_bounds__(256) void gemm_plain(
    const float* __restrict__ A, const float* __restrict__ BT,
    const float* __restrict__ bias, float* __restrict__ C)
{
    gemm_core(A, BT, bias, C, 512, nullptr);
}

__global__ __launch_bounds__(256) void gemm_conv(
    const float* __restrict__ v, const float* __restrict__ WT,
    const float* __restrict__ bias, float* __restrict__ C, const int* __restrict__ adj)
{
    gemm_core(v, WT, bias, C, 5632, adj);
}

// ---------------- weight transposes (to [n][k], tf32-rounded) ----------------
__global__ void transpose512(
    const float* __restrict__ Wq, const float* __restrict__ Wk, const float* __restrict__ Wv,
    const float* __restrict__ W2, const float* __restrict__ Wo,
    float* __restrict__ WqT, float* __restrict__ WkT, float* __restrict__ WvT,
    float* __restrict__ W2T, float* __restrict__ WoT)
{
    int z = blockIdx.z;
    const float* src = (z == 0) ? Wq : (z == 1) ? Wk : (z == 2) ? Wv : (z == 3) ? W2 : Wo;
    float* dst = (z == 0) ? WqT : (z == 1) ? WkT : (z == 2) ? WvT : (z == 3) ? W2T : WoT;
    __shared__ float s[32][33];
    int tx = threadIdx.x, ty = threadIdx.y;
    int x = blockIdx.x * 32 + tx;
#pragma unroll
    for (int j = 0; j < 4; j++) {
        int y = blockIdx.y * 32 + ty + j * 8;
        s[ty + j * 8][tx] = src[y * 512 + x];
    }
    __syncthreads();
#pragma unroll
    for (int j = 0; j < 4; j++) {
        int yo = blockIdx.x * 32 + ty + j * 8;   // n index
        dst[yo * 512 + blockIdx.y * 32 + tx] = to_tf32(s[tx][ty + j * 8]);
    }
}

// Wconv permute within row: WT[o][t*512+c] = Wconv[o][c*11+t], tf32-rounded.
__global__ void transpose_wconv(const float* __restrict__ W, float* __restrict__ WT) {
    int idx = blockIdx.x * 256 + threadIdx.x;
    if (idx >= CC * KDIM) return;
    int o = idx / KDIM, j = idx - o * KDIM;
    int t = j % 11, c = j / 11;
    WT[o * KDIM + t * 512 + c] = to_tf32(W[idx]);
}

// ---------------- 1/softplus(scale) precompute ----------------
__device__ __forceinline__ float softplusf(float x) {
    return (x > 20.f) ? x : log1pf(expf(x));
}
__global__ void invs_kernel(const float* __restrict__ scp, float* __restrict__ invs) {
    int c = blockIdx.x * 256 + threadIdx.x;
    if (c < CC) invs[c] = 1.f / softplusf(scp[c]);
}

// ---------------- q/k transform: relu+eps, *invscale, focus (cube) ----------------
__global__ void qk_focus(float* __restrict__ x, const float* __restrict__ invs) {
    int row = blockIdx.x;
    int tid = threadIdx.x; // 256
    __shared__ float red[256];
    float* p = x + row * CC;
    int c0 = tid, c1 = tid + 256;
    float v0 = (fmaxf(p[c0], 0.f) + 1e-6f) * invs[c0];
    float v1 = (fmaxf(p[c1], 0.f) + 1e-6f) * invs[c1];
    red[tid] = v0 * v0 + v1 * v1;
    __syncthreads();
    for (int o = 128; o; o >>= 1) {
        if (tid < o) red[tid] += red[tid + o];
        __syncthreads();
    }
    float nrm = sqrtf(red[0]);
    float inv = 1.f / (nrm + 1e-6f);
    float u0 = v0 * inv, u1 = v1 * inv;
    p[c0] = u0 * u0 * u0 * nrm;
    p[c1] = u1 * u1 * u1 * nrm;
}

// ---------------- kmean partials + reduce ----------------
__global__ void kmean_part(const float* __restrict__ k, float* __restrict__ kmp) {
    int b = blockIdx.y, ch = blockIdx.x;   // grid (8, BB), 512 threads
    int c = threadIdx.x;
    const float* p = k + (size_t)(b * NN + ch * 128) * CC + c;
    float s = 0.f;
    for (int n = 0; n < 128; n++) s += p[n * CC];
    kmp[(b * 8 + ch) * CC + c] = s;
}
__global__ void kmean_red(const float* __restrict__ kmp, float* __restrict__ km) {
    int i = blockIdx.x * 256 + threadIdx.x;  // BB*CC = 2048
    int b = i >> 9, c = i & 511;
    float s = 0.f;
#pragma unroll
    for (int j = 0; j < 8; j++) s += kmp[(b * 8 + j) * CC + c];
    km[i] = s * (1.f / NN);
}

// ---------------- kv partials: 8 N-splits of 128 rows each ----------------
__global__ __launch_bounds__(256) void kv_part(
    const float* __restrict__ k, const float* __restrict__ v, float* __restrict__ kvp)
{
    int bh = blockIdx.x, b = bh >> 3, h = bh & 7;
    int sp = blockIdx.y;
    __shared__ float sk[8][64], sv[8][64];
    int t = threadIdx.x;
    int dI = (t >> 4) << 2, eI = (t & 15) << 2;
    const float* kb = k + b * NN * CC + h * 64;
    const float* vb = v + b * NN * CC + h * 64;
    float acc[4][4] = {};
    int n0s = sp * 128, n0e = n0s + 128;
    for (int n0 = n0s; n0 < n0e; n0 += 8) {
#pragma unroll
        for (int j = 0; j < 2; j++) {
            int idx = t + j * 256;
            int rr = idx >> 6, cc = idx & 63;
            sk[rr][cc] = kb[(n0 + rr) * CC + cc];
            sv[rr][cc] = vb[(n0 + rr) * CC + cc];
        }
        __syncthreads();
#pragma unroll
        for (int r = 0; r < 8; r++) {
            float a[4], bv4[4];
#pragma unroll
            for (int i = 0; i < 4; i++) a[i] = sk[r][dI + i];
#pragma unroll
            for (int j = 0; j < 4; j++) bv4[j] = sv[r][eI + j];
#pragma unroll
            for (int i = 0; i < 4; i++)
#pragma unroll
                for (int j = 0; j < 4; j++)
                    acc[i][j] += a[i] * bv4[j];
        }
        __syncthreads();
    }
    float* dst = kvp + (sp * 32 + bh) * 4096;
#pragma unroll
    for (int i = 0; i < 4; i++)
#pragma unroll
        for (int j = 0; j < 4; j++)
            dst[(dI + i) * 64 + eI + j] = acc[i][j];
}

__global__ void kv_reduce(const float* __restrict__ kvp, float* __restrict__ kv) {
    int idx = blockIdx.x * 256 + threadIdx.x;   // 131072
    float s = 0.f;
#pragma unroll
    for (int sp = 0; sp < 8; sp++) s += kvp[sp * 131072 + idx];
    kv[idx] = s * (1.f / NN);
}

// ---------------- attention output + x_local add ----------------
__global__ __launch_bounds__(512) void attn_kernel(
    const float* __restrict__ q, const float* __restrict__ km,
    const float* __restrict__ kv, const float* __restrict__ xloc,
    float* __restrict__ x)
{
    int row = blockIdx.x;
    int b = row >> 10;
    int c = threadIdx.x; // 512
    __shared__ float qs[512];
    __shared__ float ps[512];
    __shared__ float zs[8];
    float qv = q[row * CC + c];
    qs[c] = qv;
    ps[c] = qv * km[b * CC + c];
    __syncthreads();
    if (c < 8) {
        float s = 0.f;
#pragma unroll
        for (int d = 0; d < 64; d++) s += ps[c * 64 + d];
        zs[c] = 1.f / (s + 1e-6f);
    }
    __syncthreads();
    int h = c >> 6, e = c & 63;
    const float* kvp = kv + ((b * 8 + h) * 64) * 64 + e;
    float acc = 0.f;
#pragma unroll 8
    for (int d = 0; d < 64; d++) acc += qs[h * 64 + d] * kvp[d * 64];
    x[row * CC + c] = acc * zs[h] + xloc[row * CC + c];
}

// ---------------- disagreement phase 1 ----------------
__global__ void disagree_part(const float* __restrict__ x, int rowsPerBlk, int rowStride,
                              int strideB, int strideH,
                              float* __restrict__ pvec, float* __restrict__ pdiag)
{
    int bh = blockIdx.x, b = bh >> 3, h = bh & 7;
    int s = blockIdx.y, S = gridDim.y;
    const float* p = x + b * strideB + h * strideH + s * rowsPerBlk * rowStride;
    int l = threadIdx.x; // 32
    float s0 = 0.f, s1 = 0.f, diag = 0.f;
    for (int n = 0; n < rowsPerBlk; n++) {
        const float* r = p + n * rowStride;
        float v0 = r[l], v1 = r[l + 32];
        float sq = v0 * v0 + v1 * v1;
#pragma unroll
        for (int o = 16; o; o >>= 1) sq += __shfl_xor_sync(0xffffffffu, sq, o);
        float inv = 1.f / fmaxf(sqrtf(sq), 1e-12f);
        float h0 = v0 * inv, h1 = v1 * inv;
        s0 += h0; s1 += h1;
        diag += h0 * h0 + h1 * h1;
    }
    float* pv = pvec + (bh * S + s) * 64;
    pv[l] = s0; pv[l + 32] = s1;
#pragma unroll
    for (int o = 16; o; o >>= 1) diag += __shfl_xor_sync(0xffffffffu, diag, o);
    if (l == 0) pdiag[bh * S + s] = diag;
}

__global__ void disagree_reduce(const float* __restrict__ pvec, const float* __restrict__ pdiag,
                                int S, double* __restrict__ Lb)
{
    int bh = blockIdx.x;
    int l = threadIdx.x; // 64
    double v = 0.0;
    for (int s = 0; s < S; s++) v += (double)pvec[(bh * S + s) * 64 + l];
    __shared__ double sh[64];
    sh[l] = v * v;
    __syncthreads();
    for (int o = 32; o; o >>= 1) {
        if (l < o) sh[l] += sh[l + o];
        __syncthreads();
    }
    if (l == 0) {
        double d = 0.0;
        for (int s = 0; s < S; s++) d += (double)pdiag[bh * S + s];
        Lb[bh] = sh[0] - d;
    }
}

__global__ void disagree_small(const float* __restrict__ x, int nRows, int rowStride,
                               int strideB, int strideH, double* __restrict__ Lb)
{
    int bh = blockIdx.x, b = bh >> 3, h = bh & 7;
    const float* p = x + b * strideB + h * strideH;
    int l = threadIdx.x; // 32
    double s0 = 0.0, s1 = 0.0, diag = 0.0;
    for (int n = 0; n < nRows; n++) {
        const float* r = p + n * rowStride;
        float v0 = r[l], v1 = r[l + 32];
        float sq = v0 * v0 + v1 * v1;
#pragma unroll
        for (int o = 16; o; o >>= 1) sq += __shfl_xor_sync(0xffffffffu, sq, o);
        float inv = 1.f / fmaxf(sqrtf(sq), 1e-12f);
        float h0 = v0 * inv, h1 = v1 * inv;
        s0 += (double)h0; s1 += (double)h1;
        diag += (double)(h0 * h0 + h1 * h1);
    }
    double val = s0 * s0 + s1 * s1;
#pragma unroll
    for (int o = 16; o; o >>= 1) {
        val += __shfl_xor_sync(0xffffffffu, val, o);
        diag += __shfl_xor_sync(0xffffffffu, diag, o);
    }
    if (l == 0) Lb[bh] = val - diag;
}

// ---------------- LayerNorm over C ----------------
__global__ void ln_kernel(const float* __restrict__ x, const float* __restrict__ g,
                          const float* __restrict__ bta, float* __restrict__ xn)
{
    int row = blockIdx.x;
    int tid = threadIdx.x; // 256
    __shared__ float rs[256], rq[256];
    const float* p = x + row * CC;
    float v0 = p[tid], v1 = p[tid + 256];
    rs[tid] = v0 + v1;
    rq[tid] = v0 * v0 + v1 * v1;
    __syncthreads();
    for (int o = 128; o; o >>= 1) {
        if (tid < o) { rs[tid] += rs[tid + o]; rq[tid] += rq[tid + o]; }
        __syncthreads();
    }
    float mu = rs[0] * (1.f / CC);
    float var = rq[0] * (1.f / CC) - mu * mu;
    float inv = rsqrtf(var + 1e-5f);
    xn[row * CC + tid] = (v0 - mu) * inv * g[tid] + bta[tid];
    xn[row * CC + tid + 256] = (v1 - mu) * inv * g[tid + 256] + bta[tid + 256];
}

// ---------------- final loss combine ----------------
__global__ void finish_loss(const double* __restrict__ Lb, float* dst, int doWrite) {
    if (doWrite && threadIdx.x == 0 && blockIdx.x == 0) {
        double l0 = 0.0, l1 = 0.0, l2 = 0.0;
        for (int i = 0; i < 32; i++) { l0 += Lb[i]; l1 += Lb[32 + i]; l2 += Lb[64 + i]; }
        double dbig = 4.0 * 8.0 * 1024.0 * 1024.0;
        double dsml = 4.0 * 8.0 * 64.0 * 64.0;
        dst[0] = (float)((l0 / dbig + l1 / dsml + l2 / dbig) / 3.0);
    }
}

// ---------------- launch ----------------
extern "C" void kernel_launch(void* const* d_in, const int* in_sizes, int n_in,
                              void* d_out, int out_size)
{
    const float* Q      = (const float*)d_in[0];
    const int*   adj    = (const int*)  d_in[1];
    const float* Wq     = (const float*)d_in[2];
    const float* bq     = (const float*)d_in[3];
    const float* Wk     = (const float*)d_in[4];
    const float* bk     = (const float*)d_in[5];
    const float* Wv     = (const float*)d_in[6];
    const float* bv     = (const float*)d_in[7];
    const float* scp    = (const float*)d_in[8];
    const float* Wconv  = (const float*)d_in[9];
    const float* bconv  = (const float*)d_in[10];
    const float* W2     = (const float*)d_in[11];
    const float* b2     = (const float*)d_in[12];
    const float* ln_g   = (const float*)d_in[13];
    const float* ln_b   = (const float*)d_in[14];
    const float* Wo     = (const float*)d_in[15];
    const float* bo     = (const float*)d_in[16];
    float* out = (float*)d_out;

    float *q, *k, *v, *WT, *WqT, *WkT, *WvT, *W2T, *WoT;
    float *conv, *xloc, *x, *xn, *km, *kmp, *kv, *kvp, *pvec, *pdiag, *invs;
    double* Lb;
    cudaGetSymbolAddress((void**)&q,     g_q);
    cudaGetSymbolAddress((void**)&k,     g_k);
    cudaGetSymbolAddress((void**)&v,     g_v);
    cudaGetSymbolAddress((void**)&WT,    g_WT);
    cudaGetSymbolAddress((void**)&WqT,   g_WqT);
    cudaGetSymbolAddress((void**)&WkT,   g_WkT);
    cudaGetSymbolAddress((void**)&WvT,   g_WvT);
    cudaGetSymbolAddress((void**)&W2T,   g_W2T);
    cudaGetSymbolAddress((void**)&WoT,   g_WoT);
    cudaGetSymbolAddress((void**)&conv,  g_conv);
    cudaGetSymbolAddress((void**)&xloc,  g_xloc);
    cudaGetSymbolAddress((void**)&x,     g_x);
    cudaGetSymbolAddress((void**)&xn,    g_xn);
    cudaGetSymbolAddress((void**)&km,    g_km);
    cudaGetSymbolAddress((void**)&kmp,   g_kmp);
    cudaGetSymbolAddress((void**)&kv,    g_kv);
    cudaGetSymbolAddress((void**)&kvp,   g_kvp);
    cudaGetSymbolAddress((void**)&pvec,  g_pvec);
    cudaGetSymbolAddress((void**)&pdiag, g_pdiag);
    cudaGetSymbolAddress((void**)&invs,  g_invs);
    cudaGetSymbolAddress((void**)&Lb,    g_lossbh);

    dim3 gG(4, 32);          // 128x128 tiles over 4096x512
    dim3 gG3(4, 32, 3);

    invs_kernel<<<2, 256>>>(scp, invs);

    // weight prep (tf32-rounded, [n][k] layout)
    transpose512<<<dim3(16, 16, 5), dim3(32, 8)>>>(Wq, Wk, Wv, W2, Wo, WqT, WkT, WvT, W2T, WoT);
    transpose_wconv<<<(CC * KDIM + 255) / 256, 256>>>(Wconv, WT);

    // projections (fused q/k/v over grid.z)
    gemm_qkv<<<gG3, 256>>>(Q, WqT, WkT, WvT, bq, bk, bv, q, k, v);

    // loss_local on head-view of v
    disagree_part<<<dim3(32, 32), 32>>>(v, NN / 32, CC, NN * CC, DD, pvec, pdiag);
    disagree_reduce<<<32, 64>>>(pvec, pdiag, 32, Lb + 0);

    // local branch: gather-fused conv GEMM then W2
    gemm_conv<<<gG, 256>>>(v, WT, bconv, conv, adj);
    gemm_plain<<<gG, 256>>>(conv, W2T, b2, xloc);

    // q/k elementwise transform
    qk_focus<<<MR, 256>>>(q, invs);
    qk_focus<<<MR, 256>>>(k, invs);

    // kmean, kv
    kmean_part<<<dim3(8, BB), 512>>>(k, kmp);
    kmean_red<<<8, 256>>>(kmp, km);
    kv_part<<<dim3(32, 8), 256>>>(k, v, kvp);
    kv_reduce<<<512, 256>>>(kvp, kv);

    // loss_kv
    disagree_small<<<32, 32>>>(kv, DD, DD, HH * DD * DD, DD * DD, Lb + 32);

    // attention out + local add
    attn_kernel<<<MR, 512>>>(q, km, kv, xloc, x);

    // loss_out on flat reshape view
    disagree_part<<<dim3(32, 32), 32>>>(x, NN / 32, DD, NN * CC, NN * CC / HH, pvec, pdiag);
    disagree_reduce<<<32, 64>>>(pvec, pdiag, 32, Lb + 64);

    // layernorm + output projection
    ln_kernel<<<MR, 256>>>(x, ln_g, ln_b, xn);
    gemm_plain<<<gG, 256>>>(xn, WoT, bo, out);

    // loss scalar appended after the (B,N,C) output, if the buffer has room
    finish_loss<<<1, 32>>>(Lb, out + MR * CC, (out_size > MR * CC) ? 1 : 0);
}